// round 13
// baseline (speedup 1.0000x reference)
#include <cuda_runtime.h>
#include <cuda_fp16.h>
#include <stdint.h>

#define N_BCH 8
#define N_ATM 10000
#define N_ELM 100
#define THREADS 768
#define NWARP  24
#define GRID_MAIN 148            // 1 CTA per SM
#define STAGES 2

#define ELM_BYTES  (N_BCH * N_ATM)              // 80000
#define TRI_N      (N_ELM * (N_ELM + 1) / 2)    // 5050
// smem layout (bytes)
#define SMEM_ACC   0                            // 8*768 floats = 24576
#define SMEM_PAIR  (8 * THREADS * 4)            // 24576; tri table 20200 -> pad 20224
#define SMEM_ELM   (SMEM_PAIR + 20224)          // 44800
#define SMEM_BUF   (SMEM_ELM + ELM_BYTES)       // 124800
#define ARR_B      (THREADS * 16)               // 12288
#define STG_B      (4 * ARR_B)                  // 49152
#define SMEM_TOTAL (SMEM_BUF + STAGES * STG_B)  // 223104

__device__ uint8_t g_elm8[ELM_BYTES];

__device__ __forceinline__ float fsqrt_approx(float x)
{
    float y;
    asm("sqrt.approx.f32 %0, %1;" : "=f"(y) : "f"(x));
    return y;
}

__device__ __forceinline__ void cp16(uint32_t saddr, const void* gptr)
{
    asm volatile("cp.async.cg.shared.global [%0], [%1], 16;\n"
                 :: "r"(saddr), "l"(gptr));
}
__device__ __forceinline__ void cp_commit()
{
    asm volatile("cp.async.commit_group;\n");
}
template <int N>
__device__ __forceinline__ void cp_wait()
{
    asm volatile("cp.async.wait_group %0;\n" :: "n"(N));
}

__device__ __forceinline__ uint32_t smem_u32(const void* p)
{
    uint32_t a;
    asm("{ .reg .u64 t; cvta.to.shared.u64 t, %1; cvt.u32.u64 %0, t; }"
        : "=r"(a) : "l"(p));
    return a;
}

// ---------------------------------------------------------------------------
// Prepass: zero outputs, convert elm int32 -> uint8 (values < 100).
// ---------------------------------------------------------------------------
__global__ void prep_kernel(const int* __restrict__ elm, float* __restrict__ out)
{
    int tid = blockIdx.x * blockDim.x + threadIdx.x;
    if (tid < N_BCH) out[tid] = 0.0f;
    for (int i = tid; i < ELM_BYTES; i += gridDim.x * blockDim.x)
        g_elm8[i] = (uint8_t)elm[i];
}

// ---------------------------------------------------------------------------
// Per-edge work: 2 u8 elm gathers + 1 half2 triangular pair gather + smem RMW.
// ---------------------------------------------------------------------------
__device__ __forceinline__ void edge_op(int n, int i, int j, float s,
                                        const uint8_t* __restrict__ elm_s,
                                        const __half2* __restrict__ pair,
                                        float* __restrict__ acc_base)
{
    int nb = n * N_ATM;
    int ea = elm_s[nb + i];
    int eb = elm_s[nb + j];
    int hi = max(ea, eb);
    int lo = min(ea, eb);
    __half2 h = pair[((hi * (hi + 1)) >> 1) + lo];
    float kk = __low2float(h);
    float R  = __high2float(h);
    float dis = fsqrt_approx(s);
    if (dis < R) {
        float d = dis - R;
        acc_base[n << 5] += kk * d * d;
    }
}

__global__ void __launch_bounds__(THREADS, 1)
close_penalty_kernel(const int4*  __restrict__ edge_n4,
                     const int4*  __restrict__ edge_i4,
                     const int4*  __restrict__ edge_j4,
                     const float4* __restrict__ sod4,
                     const int*   __restrict__ edge_n,
                     const int*   __restrict__ edge_i,
                     const int*   __restrict__ edge_j,
                     const float* __restrict__ sod,
                     const float* __restrict__ k,
                     const float* __restrict__ radius,
                     float* __restrict__ out,
                     int nvec, int E)
{
    extern __shared__ char smem[];
    float*   acc   = (float*)  (smem + SMEM_ACC);
    __half2* pair  = (__half2*)(smem + SMEM_PAIR);
    uint8_t* elm_s = (uint8_t*)(smem + SMEM_ELM);
    char*    buf   = smem + SMEM_BUF;

    int tid  = threadIdx.x;
    int lane = tid & 31;
    int wid  = tid >> 5;

    #pragma unroll
    for (int b = 0; b < 8; b++) acc[b * THREADS + tid] = 0.0f;

    // Build triangular (kk, R) half2 pair table: hi >= lo, idx = hi(hi+1)/2+lo.
    for (int idx = tid; idx < N_ELM * N_ELM; idx += THREADS) {
        int a = idx / N_ELM;       // hi candidate
        int b = idx - a * N_ELM;   // lo candidate
        if (b <= a) {
            float kk = __ldg(&k[a]) + __ldg(&k[b]);
            float R  = __ldg(&radius[a]) + __ldg(&radius[b]);
            pair[((a * (a + 1)) >> 1) + b] = __floats2half2_rn(kk, R);
        }
    }

    // Copy 80 KB u8 element table into shared memory (16B chunks).
    {
        const int4* src = (const int4*)g_elm8;
        int4*       dst = (int4*)(smem + SMEM_ELM);
        for (int i = tid; i < ELM_BYTES / 16; i += THREADS)
            dst[i] = __ldg(&src[i]);
    }
    __syncthreads();

    float* acc_base = &acc[(wid << 8) | lane];   // + (n<<5) per edge

    uint32_t my_slot = smem_u32(buf) + (uint32_t)tid * 16;

    int nblk = (nvec + THREADS - 1) / THREADS;   // blocks of 768 vec4 groups

    auto stage = [&](int blk, int s) {
        long base = (long)blk * THREADS + tid;
        if (blk < nblk && base < nvec) {
            uint32_t so = my_slot + (uint32_t)s * STG_B;
            cp16(so + 0 * ARR_B, &edge_n4[base]);
            cp16(so + 1 * ARR_B, &edge_i4[base]);
            cp16(so + 2 * ARR_B, &edge_j4[base]);
            cp16(so + 3 * ARR_B, &sod4[base]);
        }
    };

    // Prologue: fill first stage.
    stage(blockIdx.x, 0);
    cp_commit();

    // Main pipelined loop: prefetch it+1 while consuming it.
    for (int it = 0; ; it++) {
        int blk_cons = blockIdx.x + it * gridDim.x;
        if (blk_cons >= nblk) break;

        stage(blockIdx.x + (it + 1) * gridDim.x, (it + 1) % STAGES);
        cp_commit();
        cp_wait<1>();   // our stage's group is complete

        long base = (long)blk_cons * THREADS + tid;
        if (base < nvec) {
            int s = it % STAGES;
            const char* sp = buf + (size_t)s * STG_B + (size_t)tid * 16;
            int4   en = *(const int4*)  (sp + 0 * ARR_B);
            int4   ei = *(const int4*)  (sp + 1 * ARR_B);
            int4   ej = *(const int4*)  (sp + 2 * ARR_B);
            float4 sd = *(const float4*)(sp + 3 * ARR_B);

            edge_op(en.x, ei.x, ej.x, sd.x, elm_s, pair, acc_base);
            edge_op(en.y, ei.y, ej.y, sd.y, elm_s, pair, acc_base);
            edge_op(en.z, ei.z, ej.z, sd.z, elm_s, pair, acc_base);
            edge_op(en.w, ei.w, ej.w, sd.w, elm_s, pair, acc_base);
        }
    }
    cp_wait<0>();

    // Scalar tail
    int gtid = blockIdx.x * THREADS + tid;
    int t = nvec * 4 + gtid;
    if (t < E)
        edge_op(edge_n[t], edge_i[t], edge_j[t], sod[t], elm_s, pair, acc_base);

    __syncthreads();

    // Reduce: first 256 threads; thread owns (bin = tid>>5, lane).
    if (tid < 256) {
        int bin = tid >> 5;
        float sum = 0.0f;
        #pragma unroll
        for (int w = 0; w < NWARP; w++)
            sum += acc[(w << 8) + (bin << 5) + lane];
        #pragma unroll
        for (int off = 16; off > 0; off >>= 1)
            sum += __shfl_down_sync(0xFFFFFFFFu, sum, off);
        if (lane == 0)
            atomicAdd(&out[bin], sum);
    }
}

// ---------------------------------------------------------------------------
// Launch
// ---------------------------------------------------------------------------
extern "C" void kernel_launch(void* const* d_in, const int* in_sizes, int n_in,
                              void* d_out, int out_size)
{
    const int*   elm    = (const int*)  d_in[0];
    const int*   edge_n = (const int*)  d_in[1];
    const int*   edge_i = (const int*)  d_in[2];
    const int*   edge_j = (const int*)  d_in[3];
    const float* sod    = (const float*)d_in[4];
    const float* k      = (const float*)d_in[5];
    const float* radius = (const float*)d_in[6];
    float* out = (float*)d_out;

    int E    = in_sizes[1];
    int nvec = E >> 2;

    cudaFuncSetAttribute(close_penalty_kernel,
                         cudaFuncAttributeMaxDynamicSharedMemorySize, SMEM_TOTAL);

    prep_kernel<<<(ELM_BYTES + 255) / 256, 256>>>(elm, out);

    int grid = GRID_MAIN;
    int nblk = (nvec + THREADS - 1) / THREADS;
    if (nblk < grid) grid = nblk > 0 ? nblk : 1;

    close_penalty_kernel<<<grid, THREADS, SMEM_TOTAL>>>(
        (const int4*)edge_n, (const int4*)edge_i, (const int4*)edge_j,
        (const float4*)sod,
        edge_n, edge_i, edge_j, sod,
        k, radius,
        out, nvec, E);
}